// round 1
// baseline (speedup 1.0000x reference)
#include <cuda_runtime.h>
#include <cstdint>

#define T_LEN 16384
#define NXD 128
#define NHD 512
#define STEPS (T_LEN - NXD)   /* 16256 */
#define NGC (NHD * 4)         /* 2048 */

// h history: per (t,j) one u64 = (tag = t+1) << 32 | float bits of h
__device__ unsigned long long g_h64[(size_t)STEPS * NHD];   // 66 MB
// gate pre-activations, interleaved (f,i,o,c) per (t,j)
__device__ float4 g_gate4[(size_t)STEPS * NHD];             // 133 MB

__device__ __forceinline__ unsigned long long ld_acq(const unsigned long long* p) {
    unsigned long long v;
    asm volatile("ld.acquire.gpu.global.u64 %0, [%1];" : "=l"(v) : "l"(p) : "memory");
    return v;
}
__device__ __forceinline__ void st_rel(unsigned long long* p, unsigned long long v) {
    asm volatile("st.release.gpu.global.u64 [%0], %1;" :: "l"(p), "l"(v) : "memory");
}
__device__ __forceinline__ float sigm(float x) {
    return __fdividef(1.f, 1.f + __expf(-x));
}
__device__ __forceinline__ float tanh_(float x) {
    float e = __expf(-2.f * x);
    return __fdividef(1.f - e, 1.f + e);
}
__device__ __forceinline__ float dot4(float4 a, float4 b) {
    return a.x * b.x + a.y * b.y + a.z * b.z + a.w * b.w;
}

// ---------------------------------------------------------------------------
// Clear tags each launch so graph replays do full work (no cross-call caching)
// ---------------------------------------------------------------------------
__global__ void zero_kernel() {
    int idx = blockIdx.x * blockDim.x + threadIdx.x;
    int stride = gridDim.x * blockDim.x;
    for (int i = idx; i < STEPS * NHD; i += stride) g_h64[i] = 0ull;
}

// ---------------------------------------------------------------------------
// Gate pre-activation GEMM: gate[t][c] = b + sum_k W[c][k] * x[t+k]
// 64 t x 64 c tiles; Ws transposed [k][c] in smem (pad 65 to kill conflicts)
// ---------------------------------------------------------------------------
__global__ void precompute_kernel(const float* __restrict__ x,
                                  const float* __restrict__ Wf, const float* __restrict__ bf,
                                  const float* __restrict__ Wi, const float* __restrict__ bi,
                                  const float* __restrict__ Wo, const float* __restrict__ bo,
                                  const float* __restrict__ Wc, const float* __restrict__ bc) {
    __shared__ float xs[192];
    __shared__ float Ws[128][65];
    const int tBase = blockIdx.x * 64;
    const int cBase = blockIdx.y * 64;
    const int tid = threadIdx.x;

    for (int i = tid; i < 191; i += 256) xs[i] = x[tBase + i];
    for (int idx = tid; idx < 8192; idx += 256) {
        int r = idx >> 7, k = idx & 127;
        int c = cBase + r;
        int j = c >> 2, g = c & 3;
        const float* W = (g == 0) ? Wf : (g == 1) ? Wi : (g == 2) ? Wo : Wc;
        Ws[k][r] = W[j * NXD + k];
    }
    __syncthreads();

    const int tx = tid & 15, ty = tid >> 4;
    const int t0 = ty * 4, r0 = tx * 4;
    float acc[4][4] = {};
#pragma unroll 4
    for (int k = 0; k < 128; k++) {
        float a0 = xs[t0 + 0 + k], a1 = xs[t0 + 1 + k];
        float a2 = xs[t0 + 2 + k], a3 = xs[t0 + 3 + k];
        float b0 = Ws[k][r0 + 0], b1 = Ws[k][r0 + 1];
        float b2 = Ws[k][r0 + 2], b3 = Ws[k][r0 + 3];
        acc[0][0] += a0 * b0; acc[0][1] += a0 * b1; acc[0][2] += a0 * b2; acc[0][3] += a0 * b3;
        acc[1][0] += a1 * b0; acc[1][1] += a1 * b1; acc[1][2] += a1 * b2; acc[1][3] += a1 * b3;
        acc[2][0] += a2 * b0; acc[2][1] += a2 * b1; acc[2][2] += a2 * b2; acc[2][3] += a2 * b3;
        acc[3][0] += a3 * b0; acc[3][1] += a3 * b1; acc[3][2] += a3 * b2; acc[3][3] += a3 * b3;
    }
    float* out = reinterpret_cast<float*>(g_gate4);
#pragma unroll
    for (int ti = 0; ti < 4; ti++) {
#pragma unroll
        for (int cj = 0; cj < 4; cj++) {
            int t = tBase + t0 + ti;
            int c = cBase + r0 + cj;
            int j = c >> 2, g = c & 3;
            float bias = (g == 0) ? bf[j] : (g == 1) ? bi[j] : (g == 2) ? bo[j] : bc[j];
            out[(size_t)t * NGC + c] = acc[ti][cj] + bias;
        }
    }
}

// ---------------------------------------------------------------------------
// Persistent self-synchronizing recurrence.
// 128 CTAs x 128 threads. Warp w of CTA b owns h-index j = 4b + w.
// U rows for all 4 gates live in registers (64 floats/lane).
// h exchange through tagged u64 slots in L2 (release/acquire) - no barrier.
// ---------------------------------------------------------------------------
__global__ void __launch_bounds__(128, 1)
lstm_rec_kernel(const float* __restrict__ Uf, const float* __restrict__ Ui,
                const float* __restrict__ Uo, const float* __restrict__ Uc) {
    __shared__ float hs[2][NHD];
    const int tid = threadIdx.x;
    const int w = tid >> 5, l = tid & 31;
    const int j = blockIdx.x * 4 + w;

    float4 u[4][4];
#pragma unroll
    for (int m = 0; m < 4; m++) {
        int off = j * NHD + m * 128 + l * 4;
        u[0][m] = *reinterpret_cast<const float4*>(Uf + off);
        u[1][m] = *reinterpret_cast<const float4*>(Ui + off);
        u[2][m] = *reinterpret_cast<const float4*>(Uo + off);
        u[3][m] = *reinterpret_cast<const float4*>(Uc + off);
    }

    float cst = 0.f;
    float4 gx = make_float4(0.f, 0.f, 0.f, 0.f);
    if (l == 0) gx = g_gate4[j];   // gate inputs for t = 0

    for (int t = 0; t < STEPS; t++) {
        float* hb = hs[t & 1];
        if (t == 0) {
#pragma unroll
            for (int q = 0; q < 4; q++) hb[tid + q * 128] = 0.f;
        } else {
            const unsigned long long* src = g_h64 + (size_t)(t - 1) * NHD;
#pragma unroll
            for (int q = 0; q < 4; q++) {
                int s = tid + q * 128;
                unsigned long long v = ld_acq(src + s);
                while ((unsigned)(v >> 32) != (unsigned)t) v = ld_acq(src + s);
                hb[s] = __uint_as_float((unsigned)v);
            }
        }
        __syncthreads();

        float4 h0 = *reinterpret_cast<float4*>(hb + 0 + l * 4);
        float4 h1 = *reinterpret_cast<float4*>(hb + 128 + l * 4);
        float4 h2 = *reinterpret_cast<float4*>(hb + 256 + l * 4);
        float4 h3 = *reinterpret_cast<float4*>(hb + 384 + l * 4);

        float a0 = dot4(u[0][0], h0) + dot4(u[0][1], h1) + dot4(u[0][2], h2) + dot4(u[0][3], h3);
        float a1 = dot4(u[1][0], h0) + dot4(u[1][1], h1) + dot4(u[1][2], h2) + dot4(u[1][3], h3);
        float a2 = dot4(u[2][0], h0) + dot4(u[2][1], h1) + dot4(u[2][2], h2) + dot4(u[2][3], h3);
        float a3 = dot4(u[3][0], h0) + dot4(u[3][1], h1) + dot4(u[3][2], h2) + dot4(u[3][3], h3);

#pragma unroll
        for (int off = 16; off; off >>= 1) {
            a0 += __shfl_down_sync(0xffffffffu, a0, off);
            a1 += __shfl_down_sync(0xffffffffu, a1, off);
            a2 += __shfl_down_sync(0xffffffffu, a2, off);
            a3 += __shfl_down_sync(0xffffffffu, a3, off);
        }

        if (l == 0) {
            float f = sigm(gx.x + a0);
            float i = sigm(gx.y + a1);
            float o = sigm(gx.z + a2);
            float g = tanh_(gx.w + a3);
            cst = f * cst + i * g;
            float h = o * tanh_(cst);
            st_rel(g_h64 + (size_t)t * NHD + j,
                   ((unsigned long long)(unsigned)(t + 1) << 32) |
                   (unsigned long long)__float_as_uint(h));
            if (t + 1 < STEPS) gx = g_gate4[(size_t)(t + 1) * NHD + j];  // prefetch
        }
    }
}

// ---------------------------------------------------------------------------
// mu epilogue: out[t] = by + sum_j Ahy[j] * h[t][j]   (one warp per t)
// ---------------------------------------------------------------------------
__global__ void mu_kernel(const float* __restrict__ Ahy, const float* __restrict__ by,
                          float* __restrict__ out) {
    int gw = (int)((blockIdx.x * blockDim.x + threadIdx.x) >> 5);
    int l = threadIdx.x & 31;
    if (gw >= STEPS) return;
    const unsigned long long* hrow = g_h64 + (size_t)gw * NHD;
    float s = 0.f;
#pragma unroll
    for (int m = 0; m < 16; m++) {
        int idx = l + 32 * m;
        s += Ahy[idx] * __uint_as_float((unsigned)hrow[idx]);
    }
#pragma unroll
    for (int off = 16; off; off >>= 1) s += __shfl_down_sync(0xffffffffu, s, off);
    if (l == 0) out[gw] = s + by[0];
}

// ---------------------------------------------------------------------------
extern "C" void kernel_launch(void* const* d_in, const int* in_sizes, int n_in,
                              void* d_out, int out_size) {
    const float* x   = (const float*)d_in[0];
    const float* Wf  = (const float*)d_in[1];
    const float* Uf  = (const float*)d_in[2];
    const float* bf  = (const float*)d_in[3];
    const float* Wi  = (const float*)d_in[4];
    const float* Ui  = (const float*)d_in[5];
    const float* bi  = (const float*)d_in[6];
    const float* Wo  = (const float*)d_in[7];
    const float* Uo  = (const float*)d_in[8];
    const float* bo  = (const float*)d_in[9];
    const float* Wc  = (const float*)d_in[10];
    const float* Uc  = (const float*)d_in[11];
    const float* bc  = (const float*)d_in[12];
    const float* Ahy = (const float*)d_in[13];
    const float* by  = (const float*)d_in[14];
    float* out = (float*)d_out;

    zero_kernel<<<1024, 256>>>();
    precompute_kernel<<<dim3(STEPS / 64, NGC / 64), 256>>>(x, Wf, bf, Wi, bi, Wo, bo, Wc, bc);
    lstm_rec_kernel<<<NHD / 4, 128>>>(Uf, Ui, Uo, Uc);
    mu_kernel<<<(STEPS * 32 + 127) / 128, 128>>>(Ahy, by, out);
    (void)in_sizes; (void)n_in; (void)out_size;
}

// round 2
// speedup vs baseline: 1.6232x; 1.6232x over previous
#include <cuda_runtime.h>
#include <cstdint>

#define T_LEN 16384
#define NXD 128
#define NHD 512
#define STEPS (T_LEN - NXD)   /* 16256 */
#define NGC (NHD * 4)         /* 2048 */

// h history: per (t,j) one u64 = (tag = t+1) << 32 | float bits of h
__device__ unsigned long long g_h64[(size_t)STEPS * NHD];   // 66 MB
// gate pre-activations, interleaved (f,i,o,c) per (t,j)
__device__ float4 g_gate4[(size_t)STEPS * NHD];             // 133 MB

// Relaxed 64-bit exchange: tag+value share one word, so word atomicity is the
// only ordering we need — no acquire/release fences on the critical chain.
__device__ __forceinline__ unsigned long long ld_rlx(const unsigned long long* p) {
    unsigned long long v;
    asm volatile("ld.relaxed.gpu.global.u64 %0, [%1];" : "=l"(v) : "l"(p) : "memory");
    return v;
}
__device__ __forceinline__ void st_rlx(unsigned long long* p, unsigned long long v) {
    asm volatile("st.relaxed.gpu.global.u64 [%0], %1;" :: "l"(p), "l"(v) : "memory");
}
__device__ __forceinline__ float tanh_hw(float x) {
    float y;
    asm("tanh.approx.f32 %0, %1;" : "=f"(y) : "f"(x));
    return y;
}
__device__ __forceinline__ float sigm(float x) {
    return fmaf(tanh_hw(0.5f * x), 0.5f, 0.5f);
}
__device__ __forceinline__ float dot4(float4 a, float4 b) {
    return a.x * b.x + a.y * b.y + a.z * b.z + a.w * b.w;
}

// ---------------------------------------------------------------------------
// Clear tags each launch so graph replays do full work (no cross-call caching)
// ---------------------------------------------------------------------------
__global__ void zero_kernel() {
    int idx = blockIdx.x * blockDim.x + threadIdx.x;
    int stride = gridDim.x * blockDim.x;
    for (int i = idx; i < STEPS * NHD; i += stride) g_h64[i] = 0ull;
}

// ---------------------------------------------------------------------------
// Gate pre-activation GEMM: gate[t][c] = b + sum_k W[c][k] * x[t+k]
// ---------------------------------------------------------------------------
__global__ void precompute_kernel(const float* __restrict__ x,
                                  const float* __restrict__ Wf, const float* __restrict__ bf,
                                  const float* __restrict__ Wi, const float* __restrict__ bi,
                                  const float* __restrict__ Wo, const float* __restrict__ bo,
                                  const float* __restrict__ Wc, const float* __restrict__ bc) {
    __shared__ float xs[192];
    __shared__ float Ws[128][65];
    const int tBase = blockIdx.x * 64;
    const int cBase = blockIdx.y * 64;
    const int tid = threadIdx.x;

    for (int i = tid; i < 191; i += 256) xs[i] = x[tBase + i];
    for (int idx = tid; idx < 8192; idx += 256) {
        int r = idx >> 7, k = idx & 127;
        int c = cBase + r;
        int j = c >> 2, g = c & 3;
        const float* W = (g == 0) ? Wf : (g == 1) ? Wi : (g == 2) ? Wo : Wc;
        Ws[k][r] = W[j * NXD + k];
    }
    __syncthreads();

    const int tx = tid & 15, ty = tid >> 4;
    const int t0 = ty * 4, r0 = tx * 4;
    float acc[4][4] = {};
#pragma unroll 4
    for (int k = 0; k < 128; k++) {
        float a0 = xs[t0 + 0 + k], a1 = xs[t0 + 1 + k];
        float a2 = xs[t0 + 2 + k], a3 = xs[t0 + 3 + k];
        float b0 = Ws[k][r0 + 0], b1 = Ws[k][r0 + 1];
        float b2 = Ws[k][r0 + 2], b3 = Ws[k][r0 + 3];
        acc[0][0] += a0 * b0; acc[0][1] += a0 * b1; acc[0][2] += a0 * b2; acc[0][3] += a0 * b3;
        acc[1][0] += a1 * b0; acc[1][1] += a1 * b1; acc[1][2] += a1 * b2; acc[1][3] += a1 * b3;
        acc[2][0] += a2 * b0; acc[2][1] += a2 * b1; acc[2][2] += a2 * b2; acc[2][3] += a2 * b3;
        acc[3][0] += a3 * b0; acc[3][1] += a3 * b1; acc[3][2] += a3 * b2; acc[3][3] += a3 * b3;
    }
    float* out = reinterpret_cast<float*>(g_gate4);
#pragma unroll
    for (int ti = 0; ti < 4; ti++) {
#pragma unroll
        for (int cj = 0; cj < 4; cj++) {
            int t = tBase + t0 + ti;
            int c = cBase + r0 + cj;
            int j = c >> 2, g = c & 3;
            float bias = (g == 0) ? bf[j] : (g == 1) ? bi[j] : (g == 2) ? bo[j] : bc[j];
            out[(size_t)t * NGC + c] = acc[ti][cj] + bias;
        }
    }
}

// ---------------------------------------------------------------------------
// Persistent self-synchronizing recurrence.
// 128 CTAs x 128 threads. Warp w of CTA b owns h-index j = 4b + w.
// U rows for all 4 gates in registers. h exchange via relaxed tagged u64 in L2.
// All 4 slot polls per thread are kept in flight simultaneously (MLP=4).
// ---------------------------------------------------------------------------
__global__ void __launch_bounds__(128, 1)
lstm_rec_kernel(const float* __restrict__ Uf, const float* __restrict__ Ui,
                const float* __restrict__ Uo, const float* __restrict__ Uc) {
    __shared__ float hs[2][NHD];
    const int tid = threadIdx.x;
    const int w = tid >> 5, l = tid & 31;
    const int j = blockIdx.x * 4 + w;

    float4 u[4][4];
#pragma unroll
    for (int m = 0; m < 4; m++) {
        int off = j * NHD + m * 128 + l * 4;
        u[0][m] = *reinterpret_cast<const float4*>(Uf + off);
        u[1][m] = *reinterpret_cast<const float4*>(Ui + off);
        u[2][m] = *reinterpret_cast<const float4*>(Uo + off);
        u[3][m] = *reinterpret_cast<const float4*>(Uc + off);
    }

    float cst = 0.f;
    float4 gx = make_float4(0.f, 0.f, 0.f, 0.f);
    if (l == 0) gx = g_gate4[j];   // gate inputs for t = 0

    for (int t = 0; t < STEPS; t++) {
        float* hb = hs[t & 1];
        if (t == 0) {
#pragma unroll
            for (int q = 0; q < 4; q++) hb[tid + q * 128] = 0.f;
        } else {
            const unsigned long long* src = g_h64 + (size_t)(t - 1) * NHD;
            const unsigned tt = (unsigned)t;
            // issue all four polls back-to-back: 4 L2 round trips overlap
            unsigned long long v0 = ld_rlx(src + tid);
            unsigned long long v1 = ld_rlx(src + tid + 128);
            unsigned long long v2 = ld_rlx(src + tid + 256);
            unsigned long long v3 = ld_rlx(src + tid + 384);
            bool o0 = (unsigned)(v0 >> 32) == tt;
            bool o1 = (unsigned)(v1 >> 32) == tt;
            bool o2 = (unsigned)(v2 >> 32) == tt;
            bool o3 = (unsigned)(v3 >> 32) == tt;
            while (!(o0 && o1 && o2 && o3)) {
                if (!o0) { v0 = ld_rlx(src + tid);       o0 = (unsigned)(v0 >> 32) == tt; }
                if (!o1) { v1 = ld_rlx(src + tid + 128); o1 = (unsigned)(v1 >> 32) == tt; }
                if (!o2) { v2 = ld_rlx(src + tid + 256); o2 = (unsigned)(v2 >> 32) == tt; }
                if (!o3) { v3 = ld_rlx(src + tid + 384); o3 = (unsigned)(v3 >> 32) == tt; }
            }
            hb[tid]       = __uint_as_float((unsigned)v0);
            hb[tid + 128] = __uint_as_float((unsigned)v1);
            hb[tid + 256] = __uint_as_float((unsigned)v2);
            hb[tid + 384] = __uint_as_float((unsigned)v3);
        }
        __syncthreads();

        float4 h0 = *reinterpret_cast<float4*>(hb + 0   + l * 4);
        float4 h1 = *reinterpret_cast<float4*>(hb + 128 + l * 4);
        float4 h2 = *reinterpret_cast<float4*>(hb + 256 + l * 4);
        float4 h3 = *reinterpret_cast<float4*>(hb + 384 + l * 4);

        float a0 = dot4(u[0][0], h0) + dot4(u[0][1], h1) + dot4(u[0][2], h2) + dot4(u[0][3], h3);
        float a1 = dot4(u[1][0], h0) + dot4(u[1][1], h1) + dot4(u[1][2], h2) + dot4(u[1][3], h3);
        float a2 = dot4(u[2][0], h0) + dot4(u[2][1], h1) + dot4(u[2][2], h2) + dot4(u[2][3], h3);
        float a3 = dot4(u[3][0], h0) + dot4(u[3][1], h1) + dot4(u[3][2], h2) + dot4(u[3][3], h3);

#pragma unroll
        for (int off = 16; off; off >>= 1) {
            a0 += __shfl_down_sync(0xffffffffu, a0, off);
            a1 += __shfl_down_sync(0xffffffffu, a1, off);
            a2 += __shfl_down_sync(0xffffffffu, a2, off);
            a3 += __shfl_down_sync(0xffffffffu, a3, off);
        }

        if (l == 0) {
            float f = sigm(gx.x + a0);
            float i = sigm(gx.y + a1);
            float o = sigm(gx.z + a2);
            float g = tanh_hw(gx.w + a3);
            cst = f * cst + i * g;
            float h = o * tanh_hw(cst);
            st_rlx(g_h64 + (size_t)t * NHD + j,
                   ((unsigned long long)(unsigned)(t + 1) << 32) |
                   (unsigned long long)__float_as_uint(h));
            if (t + 1 < STEPS) gx = g_gate4[(size_t)(t + 1) * NHD + j];  // prefetch
        }
    }
}

// ---------------------------------------------------------------------------
// mu epilogue: out[t] = by + sum_j Ahy[j] * h[t][j]   (one warp per t)
// ---------------------------------------------------------------------------
__global__ void mu_kernel(const float* __restrict__ Ahy, const float* __restrict__ by,
                          float* __restrict__ out) {
    int gw = (int)((blockIdx.x * blockDim.x + threadIdx.x) >> 5);
    int l = threadIdx.x & 31;
    if (gw >= STEPS) return;
    const unsigned long long* hrow = g_h64 + (size_t)gw * NHD;
    float s = 0.f;
#pragma unroll
    for (int m = 0; m < 16; m++) {
        int idx = l + 32 * m;
        s += Ahy[idx] * __uint_as_float((unsigned)hrow[idx]);
    }
#pragma unroll
    for (int off = 16; off; off >>= 1) s += __shfl_down_sync(0xffffffffu, s, off);
    if (l == 0) out[gw] = s + by[0];
}

// ---------------------------------------------------------------------------
extern "C" void kernel_launch(void* const* d_in, const int* in_sizes, int n_in,
                              void* d_out, int out_size) {
    const float* x   = (const float*)d_in[0];
    const float* Wf  = (const float*)d_in[1];
    const float* Uf  = (const float*)d_in[2];
    const float* bf  = (const float*)d_in[3];
    const float* Wi  = (const float*)d_in[4];
    const float* Ui  = (const float*)d_in[5];
    const float* bi  = (const float*)d_in[6];
    const float* Wo  = (const float*)d_in[7];
    const float* Uo  = (const float*)d_in[8];
    const float* bo  = (const float*)d_in[9];
    const float* Wc  = (const float*)d_in[10];
    const float* Uc  = (const float*)d_in[11];
    const float* bc  = (const float*)d_in[12];
    const float* Ahy = (const float*)d_in[13];
    const float* by  = (const float*)d_in[14];
    float* out = (float*)d_out;

    zero_kernel<<<1024, 256>>>();
    precompute_kernel<<<dim3(STEPS / 64, NGC / 64), 256>>>(x, Wf, bf, Wi, bi, Wo, bo, Wc, bc);
    lstm_rec_kernel<<<NHD / 4, 128>>>(Uf, Ui, Uo, Uc);
    mu_kernel<<<(STEPS * 32 + 127) / 128, 128>>>(Ahy, by, out);
    (void)in_sizes; (void)n_in; (void)out_size;
}